// round 6
// baseline (speedup 1.0000x reference)
#include <cuda_runtime.h>

#define SIGMA 10.0f
#define RHO   28.0f
#define BETA  (8.0f / 3.0f)
#define DT    0.01f
#define TSTEPS 64

using u64 = unsigned long long;

// ---- packed f32x2 primitives (Blackwell FFMA2 path) ----
__device__ __forceinline__ u64 f2fma(u64 a, u64 b, u64 c) {
    u64 d; asm("fma.rn.f32x2 %0, %1, %2, %3;" : "=l"(d) : "l"(a), "l"(b), "l"(c)); return d;
}
__device__ __forceinline__ u64 f2add(u64 a, u64 b) {
    u64 d; asm("add.rn.f32x2 %0, %1, %2;" : "=l"(d) : "l"(a), "l"(b)); return d;
}
__device__ __forceinline__ u64 f2mul(u64 a, u64 b) {
    u64 d; asm("mul.rn.f32x2 %0, %1, %2;" : "=l"(d) : "l"(a), "l"(b)); return d;
}
__device__ __forceinline__ u64 pk2(float f) {
    unsigned u = __float_as_uint(f);
    return (u64)u * 0x0000000100000001ULL;
}
__device__ __forceinline__ u64 f2sub(u64 a, u64 b, u64 NEG1) { return f2fma(b, NEG1, a); }

__device__ __forceinline__ u64 f2rcp(u64 a) {
    float lo = __uint_as_float((unsigned)a);
    float hi = __uint_as_float((unsigned)(a >> 32));
    float rl, rh;
    asm("rcp.approx.f32 %0, %1;" : "=f"(rl) : "f"(lo));
    asm("rcp.approx.f32 %0, %1;" : "=f"(rh) : "f"(hi));
    return (u64)__float_as_uint(rl) | ((u64)__float_as_uint(rh) << 32);
}

__global__ void __launch_bounds__(32)
lya_spec_kernel(const float* __restrict__ x_in,
                const float* __restrict__ tseq,
                float* __restrict__ out,
                int B, int T, int write_xf)
{
    int tid = blockIdx.x * blockDim.x + threadIdx.x;
    int B2   = B >> 1;             // total packed pairs
    int half = (B2 + 1) >> 1;      // pairs handled in lane 0 of ILP
    if (tid >= half) return;

    // ---- constants (promoted to uniform registers by ptxas) ----
    const float a_f    = 1.0f - DT * SIGMA;          // 0.9
    const float s_f    = DT * SIGMA;                 // 0.1
    const float d00_f  = a_f * a_f + s_f * s_f;      // 0.82
    const float q_f    = 1.0f - DT;                  // 0.99
    const float bdt_f  = 1.0f - BETA * DT;

    const u64 NEG1    = pk2(-1.0f);
    const u64 C_NRHO  = pk2(-RHO);
    const u64 C_NBETA = pk2(-BETA);
    const u64 C_HDT   = pk2(0.5f * DT);
    const u64 C_NHDT  = pk2(-0.5f * DT);
    const u64 C_DT    = pk2(DT);
    const u64 C_NDT   = pk2(-DT);
    const u64 C_TWO   = pk2(2.0f);
    const u64 C_DT6   = pk2(DT / 6.0f);
    const u64 C_NDT6  = pk2(-DT / 6.0f);
    const u64 C_HS    = pk2(0.5f * DT * SIGMA);      // h*sigma
    const u64 C_DS    = pk2(DT * SIGMA);             // dt*sigma
    const u64 C_SD6   = pk2(DT * SIGMA / 6.0f);      // dt*sigma/6
    const u64 C_RHODT = pk2(RHO * DT);
    const u64 C_A     = pk2(a_f);
    const u64 C_S     = pk2(s_f);
    const u64 C_S99   = pk2(s_f * q_f);
    const u64 C_NI00  = pk2(-1.0f / d00_f);
    const u64 C_99SQ  = pk2(q_f * q_f);
    const u64 C_BDT2  = pk2(bdt_f * bdt_f);
    const u64 C_K     = pk2((BETA - 1.0f) * DT);
    const u64 ONE     = pk2(1.0f);

    // two independent packed pairs per thread (4 trajectories)
    const u64* xr = (const u64*)x_in;
    int rb = B2;
    int idx[2];
    idx[0] = tid;
    idx[1] = tid + half;
    bool live1 = (idx[1] < B2);
    int i1 = live1 ? idx[1] : idx[0];   // clamp to avoid OOB; result discarded

    u64 X[2], Y[2], Z[2], P1[2], P2[2];
    X[0] = xr[idx[0]];           X[1] = xr[i1];
    Y[0] = xr[rb + idx[0]];      Y[1] = xr[rb + i1];
    Z[0] = xr[2 * rb + idx[0]];  Z[1] = xr[2 * rb + i1];
    P1[0] = P1[1] = ONE;
    P2[0] = P2[1] = ONE;

    #pragma unroll 1
    for (int s = 0; s < TSTEPS; ++s) {
        #pragma unroll
        for (int j = 0; j < 2; ++j) {
            // ---------- RK4; x-channel carries sx=(y-x), sigma folded into consts;
            //            y-channel carries negated derivative (no sign flips) ----------
            u64 sx1  = f2sub(Y[j], X[j], NEG1);
            u64 nw   = f2add(Z[j], C_NRHO);              // z - rho
            u64 nk1y = f2fma(X[j], nw, Y[j]);
            u64 k1z  = f2fma(X[j], Y[j], f2mul(C_NBETA, Z[j]));

            u64 ax = f2fma(C_HS,   sx1,  X[j]);
            u64 ay = f2fma(C_NHDT, nk1y, Y[j]);
            u64 az = f2fma(C_HDT,  k1z,  Z[j]);
            u64 sx2  = f2sub(ay, ax, NEG1);
            nw       = f2add(az, C_NRHO);
            u64 nk2y = f2fma(ax, nw, ay);
            u64 k2z  = f2fma(ax, ay, f2mul(C_NBETA, az));

            ax = f2fma(C_HS,   sx2,  X[j]);
            ay = f2fma(C_NHDT, nk2y, Y[j]);
            az = f2fma(C_HDT,  k2z,  Z[j]);
            u64 sx3  = f2sub(ay, ax, NEG1);
            nw       = f2add(az, C_NRHO);
            u64 nk3y = f2fma(ax, nw, ay);
            u64 k3z  = f2fma(ax, ay, f2mul(C_NBETA, az));

            // k4 at x + dt*k2 (faithful to reference bug)
            ax = f2fma(C_DS,  sx2,  X[j]);
            ay = f2fma(C_NDT, nk2y, Y[j]);
            az = f2fma(C_DT,  k2z,  Z[j]);
            u64 sx4  = f2sub(ay, ax, NEG1);
            nw       = f2add(az, C_NRHO);
            u64 nk4y = f2fma(ax, nw, ay);
            u64 k4z  = f2fma(ax, ay, f2mul(C_NBETA, az));

            X[j] = f2fma(C_SD6,  f2fma(C_TWO, f2add(sx2,  sx3),  f2add(sx1,  sx4)),  X[j]);
            Y[j] = f2fma(C_NDT6, f2fma(C_TWO, f2add(nk2y, nk3y), f2add(nk1y, nk4y)), Y[j]);
            Z[j] = f2fma(C_DT6,  f2fma(C_TWO, f2add(k2z,  k3z),  f2add(k1z,  k4z)),  Z[j]);

            // ---------- Gram-only MGS on rows of P = I + dt*J(x) ----------
            u64 w10 = f2fma(Z[j], C_NDT, C_RHODT);       // dt*(rho - z)
            u64 xdt = f2mul(X[j], C_DT);
            u64 ydt = f2mul(Y[j], C_DT);
            u64 xx2 = f2mul(xdt, xdt);

            u64 d01 = f2fma(w10, C_A, C_S99);                    // r0.r1
            u64 d02 = f2fma(ydt, C_A, f2mul(xdt, C_S));          // r0.r2
            u64 d12 = f2fma(w10, ydt, f2mul(xdt, C_K));          // r1.r2
            u64 r1s = f2fma(w10, w10, f2add(xx2, C_99SQ));       // |r1|^2
            u64 r2s = f2fma(ydt, ydt, f2add(xx2, C_BDT2));       // |r2|^2

            u64 m01 = f2mul(d01, C_NI00);
            u64 m02 = f2mul(d02, C_NI00);

            u64 d11  = f2fma(m01, d01, r1s);
            u64 d2p  = f2fma(m02, d02, r2s);
            u64 d12p = f2fma(m02, d01, d12);

            u64 i11 = f2rcp(d11);
            u64 t   = f2mul(d12p, d12p);
            u64 u   = f2mul(t, i11);
            u64 d22 = f2fma(u, NEG1, d2p);

            P1[j] = f2mul(P1[j], d11);
            P2[j] = f2mul(P2[j], d22);
        }
    }

    // lya_k = 0.5 * log(prod n_k^2) / (t_last + dt);  lya_0 is a pure constant
    float tl = tseq[T - 1];
    float sc = __fdividef(0.5f, tl + DT);
    float ly0 = sc * (float)TSTEPS * __logf(d00_f);

    float2* o2 = (float2*)out;
    u64* o8 = (u64*)out;

    #pragma unroll
    for (int j = 0; j < 2; ++j) {
        if (j == 1 && !live1) break;
        int i = idx[j];
        o2[i] = make_float2(ly0, ly0);
        float lo = sc * __logf(__uint_as_float((unsigned)P1[j]));
        float hi = sc * __logf(__uint_as_float((unsigned)(P1[j] >> 32)));
        o2[rb + i] = make_float2(lo, hi);
        lo = sc * __logf(__uint_as_float((unsigned)P2[j]));
        hi = sc * __logf(__uint_as_float((unsigned)(P2[j] >> 32)));
        o2[2 * rb + i] = make_float2(lo, hi);
        if (write_xf) {
            o8[3 * rb + i] = X[j];
            o8[4 * rb + i] = Y[j];
            o8[5 * rb + i] = Z[j];
        }
    }
}

extern "C" void kernel_launch(void* const* d_in, const int* in_sizes, int n_in,
                              void* d_out, int out_size) {
    const float* x    = (const float*)d_in[0];
    const float* tseq = (const float*)d_in[1];
    float* out = (float*)d_out;

    int B = in_sizes[0] / 3;          // x is [3, B]
    int T = in_sizes[1];
    int write_xf = (out_size >= 6 * B) ? 1 : 0;

    int B2 = B >> 1;
    int half = (B2 + 1) >> 1;         // 2 packed pairs (4 trajectories) per thread
    int threads = 32;
    int blocks = (half + threads - 1) / threads;
    lya_spec_kernel<<<blocks, threads>>>(x, tseq, out, B, T, write_xf);
}

// round 7
// speedup vs baseline: 1.3080x; 1.3080x over previous
#include <cuda_runtime.h>

#define SIGMA 10.0f
#define RHO   28.0f
#define BETA  (8.0f / 3.0f)
#define DT    0.01f
#define TSTEPS 64

using u64 = unsigned long long;

// ---- packed f32x2 primitives (Blackwell FFMA2 path) ----
__device__ __forceinline__ u64 f2fma(u64 a, u64 b, u64 c) {
    u64 d; asm("fma.rn.f32x2 %0, %1, %2, %3;" : "=l"(d) : "l"(a), "l"(b), "l"(c)); return d;
}
__device__ __forceinline__ u64 f2add(u64 a, u64 b) {
    u64 d; asm("add.rn.f32x2 %0, %1, %2;" : "=l"(d) : "l"(a), "l"(b)); return d;
}
__device__ __forceinline__ u64 f2mul(u64 a, u64 b) {
    u64 d; asm("mul.rn.f32x2 %0, %1, %2;" : "=l"(d) : "l"(a), "l"(b)); return d;
}
__device__ __forceinline__ u64 pk2(float f) {
    unsigned u = __float_as_uint(f);
    return (u64)u * 0x0000000100000001ULL;
}
// a - b via fma(b, -1, a): stays on fma pipe
__device__ __forceinline__ u64 f2sub(u64 a, u64 b, u64 NEG1) { return f2fma(b, NEG1, a); }

__global__ void __launch_bounds__(64)
lya_spec_kernel(const float* __restrict__ x_in,
                const float* __restrict__ tseq,
                float* __restrict__ out,
                int B, int T, int write_xf)
{
    int i = blockIdx.x * blockDim.x + threadIdx.x;   // pair index
    int B2 = B >> 1;
    if (i >= B2) return;

    // ---- constants ----
    const float a_f    = 1.0f - DT * SIGMA;          // 0.9
    const float s_f    = DT * SIGMA;                 // 0.1
    const float d00_f  = a_f * a_f + s_f * s_f;      // 0.82
    const float q_f    = 1.0f - DT;                  // 0.99
    const float bdt_f  = 1.0f - BETA * DT;

    const u64 NEG1    = pk2(-1.0f);
    const u64 C_NRHO  = pk2(-RHO);
    const u64 C_NBETA = pk2(-BETA);
    const u64 C_HDT   = pk2(0.5f * DT);
    const u64 C_NHDT  = pk2(-0.5f * DT);
    const u64 C_DT    = pk2(DT);
    const u64 C_NDT   = pk2(-DT);
    const u64 C_TWO   = pk2(2.0f);
    const u64 C_DT6   = pk2(DT / 6.0f);
    const u64 C_NDT6  = pk2(-DT / 6.0f);
    const u64 C_HS    = pk2(0.5f * DT * SIGMA);      // h*sigma
    const u64 C_DS    = pk2(DT * SIGMA);             // dt*sigma
    const u64 C_SD6   = pk2(DT * SIGMA / 6.0f);      // dt*sigma/6
    const u64 C_RHODT = pk2(RHO * DT);
    const u64 C_A     = pk2(a_f);
    const u64 C_S99   = pk2(s_f * q_f);
    const u64 C_NI00  = pk2(-1.0f / d00_f);
    const u64 C_99SQ  = pk2(q_f * q_f);
    const u64 C_BDT   = pk2(bdt_f);
    const u64 C_NS    = pk2(-s_f);
    const u64 C_AQB   = pk2(a_f * q_f * bdt_f);      // const part of det
    const u64 ONE     = pk2(1.0f);

    // load 2 adjacent trajectories packed
    const u64* xr = (const u64*)x_in;
    int rb = B2;
    u64 X = xr[i];
    u64 Y = xr[rb + i];
    u64 Z = xr[2 * rb + i];

    u64 P1 = ONE;   // running product of |r1'|^2
    u64 Pd = ONE;   // running product of det(P)

    #pragma unroll 2
    for (int s = 0; s < TSTEPS; ++s) {
        // ---------- RK4; x carries sx=(y-x) (sigma folded into consts);
        //            y carries negated derivative (no sign flips) ----------
        u64 sx1  = f2sub(Y, X, NEG1);
        u64 nw   = f2add(Z, C_NRHO);                 // z - rho
        u64 nk1y = f2fma(X, nw, Y);
        u64 k1z  = f2fma(X, Y, f2mul(C_NBETA, Z));

        u64 ax = f2fma(C_HS,   sx1,  X);
        u64 ay = f2fma(C_NHDT, nk1y, Y);
        u64 az = f2fma(C_HDT,  k1z,  Z);
        u64 sx2  = f2sub(ay, ax, NEG1);
        nw       = f2add(az, C_NRHO);
        u64 nk2y = f2fma(ax, nw, ay);
        u64 k2z  = f2fma(ax, ay, f2mul(C_NBETA, az));

        ax = f2fma(C_HS,   sx2,  X);
        ay = f2fma(C_NHDT, nk2y, Y);
        az = f2fma(C_HDT,  k2z,  Z);
        u64 sx3  = f2sub(ay, ax, NEG1);
        nw       = f2add(az, C_NRHO);
        u64 nk3y = f2fma(ax, nw, ay);
        u64 k3z  = f2fma(ax, ay, f2mul(C_NBETA, az));

        // k4 at x + dt*k2 (faithful to reference bug)
        ax = f2fma(C_DS,  sx2,  X);
        ay = f2fma(C_NDT, nk2y, Y);
        az = f2fma(C_DT,  k2z,  Z);
        u64 sx4  = f2sub(ay, ax, NEG1);
        nw       = f2add(az, C_NRHO);
        u64 nk4y = f2fma(ax, nw, ay);
        u64 k4z  = f2fma(ax, ay, f2mul(C_NBETA, az));

        X = f2fma(C_SD6,  f2fma(C_TWO, f2add(sx2,  sx3),  f2add(sx1,  sx4)),  X);
        Y = f2fma(C_NDT6, f2fma(C_TWO, f2add(nk2y, nk3y), f2add(nk1y, nk4y)), Y);
        Z = f2fma(C_DT6,  f2fma(C_TWO, f2add(k2z,  k3z),  f2add(k1z,  k4z)),  Z);

        // ---------- row-1 Gram + det(P); d22 recovered via det identity ----------
        // P rows: r0=(a,s,0) const; r1=(w10, 1-dt, -xdt); r2=(ydt, xdt, 1-b*dt)
        u64 w10 = f2fma(Z, C_NDT, C_RHODT);          // dt*(rho - z)
        u64 xdt = f2mul(X, C_DT);
        u64 ydt = f2mul(Y, C_DT);
        u64 xx2 = f2mul(xdt, xdt);

        u64 d01 = f2fma(w10, C_A, C_S99);                        // r0.r1
        u64 r1s = f2fma(w10, w10, f2add(xx2, C_99SQ));           // |r1|^2
        u64 m01 = f2mul(d01, C_NI00);                            // -d01/d00
        u64 d11 = f2fma(m01, d01, r1s);                          // |r1'|^2

        // det(P) = a*q*bdt + a*xx2 - s*(w10*bdt + xdt*ydt)   (>0 on attractor)
        u64 u1  = f2fma(xdt, ydt, f2mul(w10, C_BDT));
        u64 v   = f2fma(xx2, C_A, C_AQB);
        u64 det = f2fma(u1, C_NS, v);

        P1 = f2mul(P1, d11);
        Pd = f2mul(Pd, det);
    }

    // lya0 = const;  lya1 = sc*log(P1);  lya2 = sc*(2*log(Pd) - N*log(d00) - log(P1))
    float tl = tseq[T - 1];
    float sc = __fdividef(0.5f, tl + DT);
    float ld00N = (float)TSTEPS * __logf(d00_f);
    float ly0 = sc * ld00N;

    float2* o2 = (float2*)out;
    o2[i] = make_float2(ly0, ly0);

    float lp1_lo = __logf(__uint_as_float((unsigned)P1));
    float lp1_hi = __logf(__uint_as_float((unsigned)(P1 >> 32)));
    o2[rb + i] = make_float2(sc * lp1_lo, sc * lp1_hi);

    float lpd_lo = __logf(__uint_as_float((unsigned)Pd));
    float lpd_hi = __logf(__uint_as_float((unsigned)(Pd >> 32)));
    float ly2_lo = sc * (2.0f * lpd_lo - ld00N - lp1_lo);
    float ly2_hi = sc * (2.0f * lpd_hi - ld00N - lp1_hi);
    o2[2 * rb + i] = make_float2(ly2_lo, ly2_hi);

    if (write_xf) {
        u64* o8 = (u64*)out;
        o8[3 * rb + i] = X;
        o8[4 * rb + i] = Y;
        o8[5 * rb + i] = Z;
    }
}

extern "C" void kernel_launch(void* const* d_in, const int* in_sizes, int n_in,
                              void* d_out, int out_size) {
    const float* x    = (const float*)d_in[0];
    const float* tseq = (const float*)d_in[1];
    float* out = (float*)d_out;

    int B = in_sizes[0] / 3;          // x is [3, B]
    int T = in_sizes[1];
    int write_xf = (out_size >= 6 * B) ? 1 : 0;

    int B2 = B >> 1;                  // 2 trajectories per thread
    int threads = 64;
    int blocks = (B2 + threads - 1) / threads;
    lya_spec_kernel<<<blocks, threads>>>(x, tseq, out, B, T, write_xf);
}

// round 8
// speedup vs baseline: 1.4918x; 1.1405x over previous
#include <cuda_runtime.h>

#define SIGMA 10.0f
#define RHO   28.0f
#define BETA  (8.0f / 3.0f)
#define DT    0.01f
#define TSTEPS 64

using u64 = unsigned long long;

// ---- packed f32x2 primitives (Blackwell FFMA2 path) ----
__device__ __forceinline__ u64 f2fma(u64 a, u64 b, u64 c) {
    u64 d; asm("fma.rn.f32x2 %0, %1, %2, %3;" : "=l"(d) : "l"(a), "l"(b), "l"(c)); return d;
}
__device__ __forceinline__ u64 f2add(u64 a, u64 b) {
    u64 d; asm("add.rn.f32x2 %0, %1, %2;" : "=l"(d) : "l"(a), "l"(b)); return d;
}
__device__ __forceinline__ u64 f2mul(u64 a, u64 b) {
    u64 d; asm("mul.rn.f32x2 %0, %1, %2;" : "=l"(d) : "l"(a), "l"(b)); return d;
}
__device__ __forceinline__ u64 pk2(float f) {
    unsigned u = __float_as_uint(f);
    return (u64)u * 0x0000000100000001ULL;
}
// a - b via fma(b, -1, a): stays on fma pipe
__device__ __forceinline__ u64 f2sub(u64 a, u64 b, u64 NEG1) { return f2fma(b, NEG1, a); }

__global__ void __launch_bounds__(64)
lya_spec_kernel(const float* __restrict__ x_in,
                const float* __restrict__ tseq,
                float* __restrict__ out,
                int B, int T, int write_xf)
{
    int i = blockIdx.x * blockDim.x + threadIdx.x;   // pair index
    int B2 = B >> 1;
    if (i >= B2) return;

    // ---- constants ----
    const float a_f    = 1.0f - DT * SIGMA;          // 0.9
    const float s_f    = DT * SIGMA;                 // 0.1
    const float d00_f  = a_f * a_f + s_f * s_f;      // 0.82
    const float q_f    = 1.0f - DT;                  // 0.99
    const float bdt_f  = 1.0f - BETA * DT;
    const float rs_f   = rsqrtf(d00_f);              // 1/sqrt(d00) (host-ish, computed per thread cheaply)

    const u64 NEG1    = pk2(-1.0f);
    const u64 C_NRHO  = pk2(-RHO);
    const u64 C_NIB   = pk2(-1.0f / BETA);           // -1/beta
    const u64 C_HDT   = pk2(0.5f * DT);
    const u64 C_NHDT  = pk2(-0.5f * DT);
    const u64 C_NBH   = pk2(-BETA * 0.5f * DT);      // -beta*h
    const u64 C_NBDT  = pk2(-BETA * DT);             // -beta*dt
    const u64 C_DT    = pk2(DT);
    const u64 C_NDT   = pk2(-DT);
    const u64 C_TWO   = pk2(2.0f);
    const u64 C_DT6   = pk2(DT / 6.0f);
    const u64 C_NDT6  = pk2(-DT / 6.0f);
    const u64 C_NBD6  = pk2(-BETA * DT / 6.0f);
    const u64 C_HS    = pk2(0.5f * DT * SIGMA);      // h*sigma
    const u64 C_DS    = pk2(DT * SIGMA);             // dt*sigma
    const u64 C_SD6   = pk2(DT * SIGMA / 6.0f);      // dt*sigma/6
    const u64 C_RHODT = pk2(RHO * DT);
    const u64 C_DTOB  = pk2(DT / BETA);              // dt/beta (w10 from W)
    const u64 C_E1    = pk2(s_f * rs_f);             // s/sqrt(d00)
    const u64 C_E0    = pk2(-a_f * q_f * rs_f);      // -a*q/sqrt(d00)
    const u64 C_A     = pk2(a_f);
    const u64 C_BDT   = pk2(bdt_f);
    const u64 C_NS    = pk2(-s_f);
    const u64 C_AQB   = pk2(a_f * q_f * bdt_f);      // const part of det
    const u64 ONE     = pk2(1.0f);
    const u64 C_NB    = pk2(-BETA);

    // load 2 adjacent trajectories packed
    const u64* xr = (const u64*)x_in;
    int rb = B2;
    u64 X = xr[i];
    u64 Y = xr[rb + i];
    u64 W = f2mul(xr[2 * rb + i], C_NB);   // W = -beta * z

    u64 P1 = ONE;   // running product of |r1'|^2
    u64 Pd = ONE;   // running product of det(P)

    #pragma unroll 2
    for (int s = 0; s < TSTEPS; ++s) {
        // ---------- RK4 in (X, Y, W=-beta*z) space ----------
        // k1
        u64 sx1  = f2sub(Y, X, NEG1);
        u64 nw   = f2fma(W, C_NIB, C_NRHO);          // z - rho
        u64 nk1y = f2fma(X, nw, Y);                  // -(x(rho-z)-y)
        u64 k1z  = f2fma(X, Y, W);                   // xy - beta*z

        // k2 at x + h*k1
        u64 ax = f2fma(C_HS,   sx1,  X);
        u64 ay = f2fma(C_NHDT, nk1y, Y);
        u64 aw = f2fma(k1z, C_NBH, W);               // -beta*(z + h*k1z)
        u64 sx2  = f2sub(ay, ax, NEG1);
        nw       = f2fma(aw, C_NIB, C_NRHO);
        u64 nk2y = f2fma(ax, nw, ay);
        u64 k2z  = f2fma(ax, ay, aw);

        // k3 at x + h*k2
        ax = f2fma(C_HS,   sx2,  X);
        ay = f2fma(C_NHDT, nk2y, Y);
        aw = f2fma(k2z, C_NBH, W);
        u64 sx3  = f2sub(ay, ax, NEG1);
        nw       = f2fma(aw, C_NIB, C_NRHO);
        u64 nk3y = f2fma(ax, nw, ay);
        u64 k3z  = f2fma(ax, ay, aw);

        // k4 at x + dt*k2 (faithful to reference bug)
        ax = f2fma(C_DS,  sx2,  X);
        ay = f2fma(C_NDT, nk2y, Y);
        aw = f2fma(k2z, C_NBDT, W);
        u64 sx4  = f2sub(ay, ax, NEG1);
        nw       = f2fma(aw, C_NIB, C_NRHO);
        u64 nk4y = f2fma(ax, nw, ay);
        u64 k4z  = f2fma(ax, ay, aw);

        X = f2fma(C_SD6,  f2fma(C_TWO, f2add(sx2,  sx3),  f2add(sx1,  sx4)),  X);
        Y = f2fma(C_NDT6, f2fma(C_TWO, f2add(nk2y, nk3y), f2add(nk1y, nk4y)), Y);
        W = f2fma(C_NBD6, f2fma(C_TWO, f2add(k2z,  k3z),  f2add(k1z,  k4z)),  W);

        // ---------- Gram row-1 (closed form) + det(P) ----------
        // w10 = dt*(rho - z) = rho*dt + (dt/beta)*W
        u64 w10 = f2fma(W, C_DTOB, C_RHODT);
        u64 xdt = f2mul(X, C_DT);
        u64 ydt = f2mul(Y, C_DT);
        u64 xx2 = f2mul(xdt, xdt);

        // d11 = xx2 + (s*w10 - a*q)^2 / d00
        u64 e   = f2fma(w10, C_E1, C_E0);
        u64 d11 = f2fma(e, e, xx2);

        // det(P) = a*q*bdt + a*xx2 - s*(w10*bdt + xdt*ydt)
        u64 u1  = f2fma(xdt, ydt, f2mul(w10, C_BDT));
        u64 v   = f2fma(xx2, C_A, C_AQB);
        u64 det = f2fma(u1, C_NS, v);

        P1 = f2mul(P1, d11);
        Pd = f2mul(Pd, det);
    }

    // lya0 = const;  lya1 = sc*log(P1);  lya2 = sc*(2*log(Pd) - N*log(d00) - log(P1))
    float tl = tseq[T - 1];
    float sc = __fdividef(0.5f, tl + DT);
    float ld00N = (float)TSTEPS * __logf(d00_f);
    float ly0 = sc * ld00N;

    float2* o2 = (float2*)out;
    o2[i] = make_float2(ly0, ly0);

    float lp1_lo = __logf(__uint_as_float((unsigned)P1));
    float lp1_hi = __logf(__uint_as_float((unsigned)(P1 >> 32)));
    o2[rb + i] = make_float2(sc * lp1_lo, sc * lp1_hi);

    float lpd_lo = __logf(__uint_as_float((unsigned)Pd));
    float lpd_hi = __logf(__uint_as_float((unsigned)(Pd >> 32)));
    o2[2 * rb + i] = make_float2(sc * (2.0f * lpd_lo - ld00N - lp1_lo),
                                 sc * (2.0f * lpd_hi - ld00N - lp1_hi));

    if (write_xf) {
        u64* o8 = (u64*)out;
        o8[3 * rb + i] = X;
        o8[4 * rb + i] = Y;
        o8[5 * rb + i] = f2mul(W, C_NIB);   // z = -W/beta
    }
}

extern "C" void kernel_launch(void* const* d_in, const int* in_sizes, int n_in,
                              void* d_out, int out_size) {
    const float* x    = (const float*)d_in[0];
    const float* tseq = (const float*)d_in[1];
    float* out = (float*)d_out;

    int B = in_sizes[0] / 3;          // x is [3, B]
    int T = in_sizes[1];
    int write_xf = (out_size >= 6 * B) ? 1 : 0;

    int B2 = B >> 1;                  // 2 trajectories per thread
    int threads = 64;
    int blocks = (B2 + threads - 1) / threads;
    lya_spec_kernel<<<blocks, threads>>>(x, tseq, out, B, T, write_xf);
}